// round 13
// baseline (speedup 1.0000x reference)
#include <cuda_runtime.h>

#define H      128
#define W      128
#define NLAM   128
#define BATCH  16
#define NK     4
#define HP     192
#define WP     192

#define QTRSZ (BATCH * NK * HP * WP)
// four quarter-lambda accumulators: 4 x 9.4 MB
__device__ float g_acc[4 * QTRSZ];

// ---------------------------------------------------------------------------
// Kernel 1: accumulate shifted slices over one quarter (32) of the wavelengths.
// Block: 192 threads = 6 warps laid out 3(x) x 2(y); warp = 64 cols x 8 rows
// (lane owns 2 consecutive cols as float2). Grid (1, 12, 256). 3072 blocks.
// Live-lambda interval per warp via ballot; counted loop unrolled x4 for MLP.
// ---------------------------------------------------------------------------
__global__ __launch_bounds__(192) void accum_kernel(
    const float* __restrict__ cube,   // (B, NLAM, H, W)
    const float* __restrict__ dx,     // (NK, NLAM)
    const float* __restrict__ dy)     // (NK, NLAM)
{
    __shared__ int    s_nx[32], s_ny[32];
    __shared__ float4 s_w[32];        // (fx, gx, fy, gy)

    const int bz = blockIdx.z;
    const int lq = bz & 3;            // lambda quarter
    const int bk = bz >> 2;           // b*4 + k
    const int b  = bk >> 2;
    const int k  = bk & 3;
    const int l0 = lq * 32;

    const int tid = threadIdx.y * 32 + threadIdx.x;
    if (tid < 32) {
        float dxv = dx[k * NLAM + l0 + tid];
        float dyv = dy[k * NLAM + l0 + tid];
        float nxf = floorf(dxv), nyf = floorf(dyv);
        s_nx[tid] = (int)nxf;
        s_ny[tid] = (int)nyf;
        float fx = dxv - nxf, fy = dyv - nyf;
        s_w[tid] = make_float4(fx, 1.0f - fx, fy, 1.0f - fy);
    }
    __syncthreads();

    const int wid  = tid >> 5;        // 0..5
    const int lane = tid & 31;
    const int wx   = wid % 3;         // x warp-tile
    const int wy   = wid / 3;         // y warp-tile
    const int x0w  = wx * 64;         // warp col base
    const int y0   = blockIdx.y * 16 + wy * 8;   // warp row base

    float a0[8], a1[8];
    #pragma unroll
    for (int i = 0; i < 8; ++i) { a0[i] = 0.0f; a1[i] = 0.0f; }

    const float* cb = cube + ((size_t)b * NLAM + l0) * (H * W);

    if (k == 0) {
        // pure horizontal: input row = y - 32 (fixed), 8 rows ry0..ry0+7
        const int ry0 = y0 - 32;
        if (!(ry0 > H - 1 || ry0 + 7 < 0)) {
            const bool rint = (ry0 >= 0) & (ry0 + 7 <= H - 1);

            unsigned mask;
            {
                int tl = x0w - 33 - s_nx[lane];
                bool live = !(tl > W - 1 || tl + 64 < 0);
                mask = __ballot_sync(0xffffffffu, live);
            }
            const int lmin = __ffs(mask) - 1;
            const int cnt  = __popc(mask);

            #pragma unroll 4
            for (int i = 0; i < cnt; ++i) {
                const int l  = lmin + i;
                const int nx = s_nx[l];
                const int t  = x0w - 33 - nx;          // cols t..t+64

                const float4 wv = s_w[l];
                const float fx = wv.x, gx = wv.y;
                const float* sl = cb + l * (H * W);
                const int o  = t & 1;
                const int ta = t - o;
                const int ca = ta + 2 * lane;
                const bool interior = (ta >= 0) & (t + 64 <= W - 1) & rint;

                if (interior) {
                    const float* rp = sl + ry0 * W + ca;
                    if (o == 0) {
                        #pragma unroll
                        for (int j = 0; j < 8; ++j) {
                            const float* rj = rp + j * W;
                            float2 A = __ldg((const float2*)rj);
                            float  c = __ldg(rj + 2);
                            a0[j] += fx * A.x + gx * A.y;
                            a1[j] += fx * A.y + gx * c;
                        }
                    } else {
                        #pragma unroll
                        for (int j = 0; j < 8; ++j) {
                            const float* rj = rp + j * W;
                            float2 A = __ldg((const float2*)rj);
                            float2 B = __ldg((const float2*)(rj + 2));
                            a0[j] += fx * A.y + gx * B.x;
                            a1[j] += fx * B.x + gx * B.y;
                        }
                    }
                } else {
                    const int c0 = t + 2 * lane;
                    const bool cv0 = ((unsigned)c0       < (unsigned)W);
                    const bool cv1 = ((unsigned)(c0 + 1) < (unsigned)W);
                    const bool cv2 = ((unsigned)(c0 + 2) < (unsigned)W);
                    #pragma unroll
                    for (int j = 0; j < 8; ++j) {
                        int row = ry0 + j;
                        bool rv = ((unsigned)row < (unsigned)H);
                        const float* rj = sl + row * W + c0;
                        float v0 = (rv && cv0) ? __ldg(rj)     : 0.0f;
                        float v1 = (rv && cv1) ? __ldg(rj + 1) : 0.0f;
                        float v2 = (rv && cv2) ? __ldg(rj + 2) : 0.0f;
                        a0[j] += fx * v0 + gx * v1;
                        a1[j] += fx * v1 + gx * v2;
                    }
                }
            }
        }
    } else if (k == 1) {
        // pure vertical: dominant x-tap only (minor tap weight <= 1.8e-6)
        unsigned mask;
        {
            int l = lane;
            const float4 wv = s_w[l];
            int coff = (wv.x >= 0.5f) ? (-33 - s_nx[l]) : (-32 - s_nx[l]);
            int cbase = x0w + coff;
            int ry0l  = y0 - 33 - s_ny[l];
            bool live = !(ry0l > H - 1 || ry0l + 8 < 0 ||
                          cbase > W - 1 || cbase + 63 < 0);
            mask = __ballot_sync(0xffffffffu, live);
        }
        const int lmin = __ffs(mask) - 1;
        const int cnt  = __popc(mask);

        #pragma unroll 4
        for (int i = 0; i < cnt; ++i) {
            const int l   = lmin + i;
            const int ny  = s_ny[l];
            const int ry0 = y0 - 33 - ny;

            const float4 wv = s_w[l];
            int coff; float wdom;
            if (wv.x >= 0.5f) { coff = -33 - s_nx[l]; wdom = wv.x; }   // fx tap
            else              { coff = -32 - s_nx[l]; wdom = wv.y; }   // gx tap
            const int cbase = x0w + coff;      // warp cols cbase..cbase+63

            const float fy = wv.z * wdom;
            const float gy = wv.w * wdom;
            const float* sl = cb + l * (H * W);
            const int cc = cbase + 2 * lane;
            const bool interior = ((cbase & 1) == 0) &
                                  (cbase >= 0) & (cbase + 63 <= W - 1) &
                                  (ry0 >= 0) & (ry0 + 8 <= H - 1);

            if (interior) {
                const float* rp = sl + ry0 * W + cc;
                float2 vp = __ldg((const float2*)rp);
                #pragma unroll
                for (int j = 1; j <= 8; ++j) {
                    float2 vc = __ldg((const float2*)(rp + j * W));
                    a0[j - 1] += fy * vp.x + gy * vc.x;
                    a1[j - 1] += fy * vp.y + gy * vc.y;
                    vp = vc;
                }
            } else {
                const bool cv0 = ((unsigned)cc       < (unsigned)W);
                const bool cv1 = ((unsigned)(cc + 1) < (unsigned)W);
                float p0, p1;
                {
                    bool rv = ((unsigned)ry0 < (unsigned)H);
                    const float* rj = sl + ry0 * W + cc;
                    p0 = (rv && cv0) ? __ldg(rj)     : 0.0f;
                    p1 = (rv && cv1) ? __ldg(rj + 1) : 0.0f;
                }
                #pragma unroll
                for (int j = 1; j <= 8; ++j) {
                    int row = ry0 + j;
                    bool rv = ((unsigned)row < (unsigned)H);
                    const float* rj = sl + row * W + cc;
                    float c0 = (rv && cv0) ? __ldg(rj)     : 0.0f;
                    float c1 = (rv && cv1) ? __ldg(rj + 1) : 0.0f;
                    a0[j - 1] += fy * p0 + gy * c0;
                    a1[j - 1] += fy * p1 + gy * c1;
                    p0 = c0; p1 = c1;
                }
            }
        }
    } else {
        // full bilinear 4-tap (k = 2, 3)
        unsigned mask;
        {
            int l = lane;
            int tl   = x0w - 33 - s_nx[l];
            int ry0l = y0  - 33 - s_ny[l];
            bool live = !(tl > W - 1 || tl + 64 < 0 ||
                          ry0l > H - 1 || ry0l + 8 < 0);
            mask = __ballot_sync(0xffffffffu, live);
        }
        const int lmin = __ffs(mask) - 1;
        const int cnt  = __popc(mask);

        #pragma unroll 4
        for (int i = 0; i < cnt; ++i) {
            const int l   = lmin + i;
            const int nx  = s_nx[l];
            const int ny  = s_ny[l];
            const int t   = x0w - 33 - nx;
            const int ry0 = y0  - 33 - ny;

            const float4 wv = s_w[l];
            const float fx = wv.x, gx = wv.y, fy = wv.z, gy = wv.w;
            const float* sl = cb + l * (H * W);

            const int o  = t & 1;
            const int ta = t - o;
            const int ca = ta + 2 * lane;
            const bool interior = (ta >= 0) & (t + 64 <= W - 1) &
                                  (ry0 >= 0) & (ry0 + 8 <= H - 1);

            float hp0, hp1;

            if (interior) {
                const float* rp = sl + ry0 * W + ca;
                if (o == 0) {
                    {
                        float2 A = __ldg((const float2*)rp);
                        float  c = __ldg(rp + 2);
                        hp0 = fx * A.x + gx * A.y;
                        hp1 = fx * A.y + gx * c;
                    }
                    #pragma unroll
                    for (int j = 1; j <= 8; ++j) {
                        const float* rj = rp + j * W;
                        float2 A = __ldg((const float2*)rj);
                        float  c = __ldg(rj + 2);
                        float hc0 = fx * A.x + gx * A.y;
                        float hc1 = fx * A.y + gx * c;
                        a0[j - 1] += fy * hp0 + gy * hc0;
                        a1[j - 1] += fy * hp1 + gy * hc1;
                        hp0 = hc0; hp1 = hc1;
                    }
                } else {
                    {
                        float2 A = __ldg((const float2*)rp);
                        float2 B = __ldg((const float2*)(rp + 2));
                        hp0 = fx * A.y + gx * B.x;
                        hp1 = fx * B.x + gx * B.y;
                    }
                    #pragma unroll
                    for (int j = 1; j <= 8; ++j) {
                        const float* rj = rp + j * W;
                        float2 A = __ldg((const float2*)rj);
                        float2 B = __ldg((const float2*)(rj + 2));
                        float hc0 = fx * A.y + gx * B.x;
                        float hc1 = fx * B.x + gx * B.y;
                        a0[j - 1] += fy * hp0 + gy * hc0;
                        a1[j - 1] += fy * hp1 + gy * hc1;
                        hp0 = hc0; hp1 = hc1;
                    }
                }
            } else {
                const int c0 = t + 2 * lane;
                const bool cv0 = ((unsigned)c0       < (unsigned)W);
                const bool cv1 = ((unsigned)(c0 + 1) < (unsigned)W);
                const bool cv2 = ((unsigned)(c0 + 2) < (unsigned)W);
                {
                    bool rv = ((unsigned)ry0 < (unsigned)H);
                    const float* rj = sl + ry0 * W + c0;
                    float v0 = (rv && cv0) ? __ldg(rj)     : 0.0f;
                    float v1 = (rv && cv1) ? __ldg(rj + 1) : 0.0f;
                    float v2 = (rv && cv2) ? __ldg(rj + 2) : 0.0f;
                    hp0 = fx * v0 + gx * v1;
                    hp1 = fx * v1 + gx * v2;
                }
                #pragma unroll
                for (int j = 1; j <= 8; ++j) {
                    int row = ry0 + j;
                    bool rv = ((unsigned)row < (unsigned)H);
                    const float* rj = sl + row * W + c0;
                    float v0 = (rv && cv0) ? __ldg(rj)     : 0.0f;
                    float v1 = (rv && cv1) ? __ldg(rj + 1) : 0.0f;
                    float v2 = (rv && cv2) ? __ldg(rj + 2) : 0.0f;
                    float hc0 = fx * v0 + gx * v1;
                    float hc1 = fx * v1 + gx * v2;
                    a0[j - 1] += fy * hp0 + gy * hc0;
                    a1[j - 1] += fy * hp1 + gy * hc1;
                    hp0 = hc0; hp1 = hc1;
                }
            }
        }
    }

    float* ap = g_acc + (size_t)lq * QTRSZ + ((size_t)bk * HP + y0) * WP + x0w + 2 * lane;
    #pragma unroll
    for (int i = 0; i < 8; ++i)
        *(float2*)(ap + i * WP) = make_float2(a0[i], a1[i]);
}

// ---------------------------------------------------------------------------
// Kernel 2: 7x7 PSF convolution (same padding, zeros), sum of 4 acc -> out.
// Block: (32, 8), output tile 32x32. Grid: (6, 6, B*NK).
// smem fill uses strided 2-D indexing (no div/mod); 4 quarter loads batched.
// ---------------------------------------------------------------------------
__global__ __launch_bounds__(256) void conv_kernel(
    const float* __restrict__ psf,
    float* __restrict__ out)
{
    __shared__ float s[38 * 40];
    __shared__ float sp[49];

    const int bz = blockIdx.z;
    const float* ap0 = g_acc + (size_t)bz * HP * WP;

    const int tx  = threadIdx.x;
    const int ty  = threadIdx.y;
    const int tid = ty * 32 + tx;
    if (tid < 49) sp[tid] = psf[tid];

    const int x0 = blockIdx.x * 32;
    const int y0 = blockIdx.y * 32;

    #pragma unroll
    for (int r = 0; r < 40; r += 8) {
        int rr = r + ty;
        if (rr < 38) {
            int gy = y0 + rr - 3;
            bool okr = ((unsigned)gy < (unsigned)HP);
            #pragma unroll
            for (int cblk = 0; cblk < 2; ++cblk) {
                int c = tx + cblk * 32;
                if (c < 38) {
                    int gx = x0 + c - 3;
                    bool ok = okr && ((unsigned)gx < (unsigned)WP);
                    float v = 0.0f;
                    if (ok) {
                        int idx = gy * WP + gx;
                        float q0 = __ldg(ap0 + idx);
                        float q1 = __ldg(ap0 + idx + QTRSZ);
                        float q2 = __ldg(ap0 + idx + 2 * QTRSZ);
                        float q3 = __ldg(ap0 + idx + 3 * QTRSZ);
                        v = (q0 + q1) + (q2 + q3);
                    }
                    s[rr * 40 + c] = v;
                }
            }
        }
    }
    __syncthreads();

    float w[49];
    #pragma unroll
    for (int i = 0; i < 49; ++i) w[i] = sp[i];

    const int rbase = ty * 4;

    float a0 = 0.f, a1 = 0.f, a2 = 0.f, a3 = 0.f;
    #pragma unroll
    for (int rr = 0; rr < 10; ++rr) {
        #pragma unroll
        for (int v = 0; v < 7; ++v) {
            float xv = s[(rbase + rr) * 40 + tx + v];
            if (rr <= 6)            a0 += w[rr * 7 + v] * xv;
            if (rr >= 1 && rr <= 7) a1 += w[(rr - 1) * 7 + v] * xv;
            if (rr >= 2 && rr <= 8) a2 += w[(rr - 2) * 7 + v] * xv;
            if (rr >= 3)            a3 += w[(rr - 3) * 7 + v] * xv;
        }
    }

    float* op = out + ((size_t)bz * HP + y0 + rbase) * WP + x0 + tx;
    op[0 * WP] = a0;
    op[1 * WP] = a1;
    op[2 * WP] = a2;
    op[3 * WP] = a3;
}

extern "C" void kernel_launch(void* const* d_in, const int* in_sizes, int n_in,
                              void* d_out, int out_size)
{
    const float* cube = (const float*)d_in[0];
    const float* psf  = (const float*)d_in[1];
    const float* dx   = (const float*)d_in[2];
    const float* dy   = (const float*)d_in[3];
    float* out = (float*)d_out;

    dim3 ga(1, 12, BATCH * NK * 4), ta(32, 6);   // 3072 blocks, 192 thr
    accum_kernel<<<ga, ta>>>(cube, dx, dy);

    dim3 gc(6, 6, BATCH * NK), tc(32, 8);
    conv_kernel<<<gc, tc>>>(psf, out);
}

// round 14
// speedup vs baseline: 1.4097x; 1.4097x over previous
#include <cuda_runtime.h>

#define H      128
#define W      128
#define NLAM   128
#define BATCH  16
#define NK     4
#define HP     192
#define WP     192

#define QTRSZ (BATCH * NK * HP * WP)
// four quarter-lambda accumulators: 4 x 9.4 MB
__device__ float g_acc[4 * QTRSZ];

// ---------------------------------------------------------------------------
// Kernel 1: accumulate shifted slices over one quarter (32) of the wavelengths.
// Block: 192 threads = 6 warps laid out 3(x) x 2(y); warp = 64 cols x 4 rows
// (lane owns 2 consecutive cols as float2). Block = 192 cols x 8 rows.
// Grid (1, 24, 256): z = (b*4 + k)*4 + lq. 6144 blocks (~2 waves).
// Live-lambda interval per warp via ballot; counted loop unrolled x2.
// ---------------------------------------------------------------------------
__global__ __launch_bounds__(192) void accum_kernel(
    const float* __restrict__ cube,   // (B, NLAM, H, W)
    const float* __restrict__ dx,     // (NK, NLAM)
    const float* __restrict__ dy)     // (NK, NLAM)
{
    __shared__ int    s_nx[32], s_ny[32];
    __shared__ float4 s_w[32];        // (fx, gx, fy, gy)

    const int bz = blockIdx.z;
    const int lq = bz & 3;            // lambda quarter
    const int bk = bz >> 2;           // b*4 + k
    const int b  = bk >> 2;
    const int k  = bk & 3;
    const int l0 = lq * 32;

    const int tid = threadIdx.y * 32 + threadIdx.x;
    if (tid < 32) {
        float dxv = dx[k * NLAM + l0 + tid];
        float dyv = dy[k * NLAM + l0 + tid];
        float nxf = floorf(dxv), nyf = floorf(dyv);
        s_nx[tid] = (int)nxf;
        s_ny[tid] = (int)nyf;
        float fx = dxv - nxf, fy = dyv - nyf;
        s_w[tid] = make_float4(fx, 1.0f - fx, fy, 1.0f - fy);
    }
    __syncthreads();

    const int wid  = tid >> 5;        // 0..5
    const int lane = tid & 31;
    const int wx   = wid % 3;         // x warp-tile
    const int wy   = wid / 3;         // y warp-tile (0..1)
    const int x0w  = wx * 64;         // warp col base
    const int y0   = blockIdx.y * 8 + wy * 4;    // warp row base (4 rows)

    float a0[4], a1[4];
    #pragma unroll
    for (int i = 0; i < 4; ++i) { a0[i] = 0.0f; a1[i] = 0.0f; }

    const float* cb = cube + ((size_t)b * NLAM + l0) * (H * W);

    if (k == 0) {
        // pure horizontal: input row = y - 32 (fixed), 4 rows ry0..ry0+3
        const int ry0 = y0 - 32;
        if (!(ry0 > H - 1 || ry0 + 3 < 0)) {
            const bool rint = (ry0 >= 0) & (ry0 + 3 <= H - 1);

            unsigned mask;
            {
                int tl = x0w - 33 - s_nx[lane];
                bool live = !(tl > W - 1 || tl + 64 < 0);
                mask = __ballot_sync(0xffffffffu, live);
            }
            const int lmin = __ffs(mask) - 1;
            const int cnt  = __popc(mask);

            #pragma unroll 2
            for (int i = 0; i < cnt; ++i) {
                const int l  = lmin + i;
                const int nx = s_nx[l];
                const int t  = x0w - 33 - nx;          // cols t..t+64

                const float4 wv = s_w[l];
                const float fx = wv.x, gx = wv.y;
                const float* sl = cb + l * (H * W);
                const int o  = t & 1;
                const int ta = t - o;
                const int ca = ta + 2 * lane;
                const bool interior = (ta >= 0) & (t + 64 <= W - 1) & rint;

                if (interior) {
                    const float* rp = sl + ry0 * W + ca;
                    if (o == 0) {
                        #pragma unroll
                        for (int j = 0; j < 4; ++j) {
                            const float* rj = rp + j * W;
                            float2 A = __ldg((const float2*)rj);
                            float  c = __ldg(rj + 2);
                            a0[j] += fx * A.x + gx * A.y;
                            a1[j] += fx * A.y + gx * c;
                        }
                    } else {
                        #pragma unroll
                        for (int j = 0; j < 4; ++j) {
                            const float* rj = rp + j * W;
                            float2 A = __ldg((const float2*)rj);
                            float2 B = __ldg((const float2*)(rj + 2));
                            a0[j] += fx * A.y + gx * B.x;
                            a1[j] += fx * B.x + gx * B.y;
                        }
                    }
                } else {
                    const int c0 = t + 2 * lane;
                    const bool cv0 = ((unsigned)c0       < (unsigned)W);
                    const bool cv1 = ((unsigned)(c0 + 1) < (unsigned)W);
                    const bool cv2 = ((unsigned)(c0 + 2) < (unsigned)W);
                    #pragma unroll
                    for (int j = 0; j < 4; ++j) {
                        int row = ry0 + j;
                        bool rv = ((unsigned)row < (unsigned)H);
                        const float* rj = sl + row * W + c0;
                        float v0 = (rv && cv0) ? __ldg(rj)     : 0.0f;
                        float v1 = (rv && cv1) ? __ldg(rj + 1) : 0.0f;
                        float v2 = (rv && cv2) ? __ldg(rj + 2) : 0.0f;
                        a0[j] += fx * v0 + gx * v1;
                        a1[j] += fx * v1 + gx * v2;
                    }
                }
            }
        }
    } else if (k == 1) {
        // pure vertical: dominant x-tap only (minor tap weight <= 1.8e-6)
        unsigned mask;
        {
            int l = lane;
            const float4 wv = s_w[l];
            int coff = (wv.x >= 0.5f) ? (-33 - s_nx[l]) : (-32 - s_nx[l]);
            int cbase = x0w + coff;
            int ry0l  = y0 - 33 - s_ny[l];
            bool live = !(ry0l > H - 1 || ry0l + 4 < 0 ||
                          cbase > W - 1 || cbase + 63 < 0);
            mask = __ballot_sync(0xffffffffu, live);
        }
        const int lmin = __ffs(mask) - 1;
        const int cnt  = __popc(mask);

        #pragma unroll 2
        for (int i = 0; i < cnt; ++i) {
            const int l   = lmin + i;
            const int ny  = s_ny[l];
            const int ry0 = y0 - 33 - ny;

            const float4 wv = s_w[l];
            int coff; float wdom;
            if (wv.x >= 0.5f) { coff = -33 - s_nx[l]; wdom = wv.x; }   // fx tap
            else              { coff = -32 - s_nx[l]; wdom = wv.y; }   // gx tap
            const int cbase = x0w + coff;      // warp cols cbase..cbase+63

            const float fy = wv.z * wdom;
            const float gy = wv.w * wdom;
            const float* sl = cb + l * (H * W);
            const int cc = cbase + 2 * lane;
            const bool interior = ((cbase & 1) == 0) &
                                  (cbase >= 0) & (cbase + 63 <= W - 1) &
                                  (ry0 >= 0) & (ry0 + 4 <= H - 1);

            if (interior) {
                const float* rp = sl + ry0 * W + cc;
                float2 vp = __ldg((const float2*)rp);
                #pragma unroll
                for (int j = 1; j <= 4; ++j) {
                    float2 vc = __ldg((const float2*)(rp + j * W));
                    a0[j - 1] += fy * vp.x + gy * vc.x;
                    a1[j - 1] += fy * vp.y + gy * vc.y;
                    vp = vc;
                }
            } else {
                const bool cv0 = ((unsigned)cc       < (unsigned)W);
                const bool cv1 = ((unsigned)(cc + 1) < (unsigned)W);
                float p0, p1;
                {
                    bool rv = ((unsigned)ry0 < (unsigned)H);
                    const float* rj = sl + ry0 * W + cc;
                    p0 = (rv && cv0) ? __ldg(rj)     : 0.0f;
                    p1 = (rv && cv1) ? __ldg(rj + 1) : 0.0f;
                }
                #pragma unroll
                for (int j = 1; j <= 4; ++j) {
                    int row = ry0 + j;
                    bool rv = ((unsigned)row < (unsigned)H);
                    const float* rj = sl + row * W + cc;
                    float c0 = (rv && cv0) ? __ldg(rj)     : 0.0f;
                    float c1 = (rv && cv1) ? __ldg(rj + 1) : 0.0f;
                    a0[j - 1] += fy * p0 + gy * c0;
                    a1[j - 1] += fy * p1 + gy * c1;
                    p0 = c0; p1 = c1;
                }
            }
        }
    } else {
        // full bilinear 4-tap (k = 2, 3)
        unsigned mask;
        {
            int l = lane;
            int tl   = x0w - 33 - s_nx[l];
            int ry0l = y0  - 33 - s_ny[l];
            bool live = !(tl > W - 1 || tl + 64 < 0 ||
                          ry0l > H - 1 || ry0l + 4 < 0);
            mask = __ballot_sync(0xffffffffu, live);
        }
        const int lmin = __ffs(mask) - 1;
        const int cnt  = __popc(mask);

        #pragma unroll 2
        for (int i = 0; i < cnt; ++i) {
            const int l   = lmin + i;
            const int nx  = s_nx[l];
            const int ny  = s_ny[l];
            const int t   = x0w - 33 - nx;
            const int ry0 = y0  - 33 - ny;

            const float4 wv = s_w[l];
            const float fx = wv.x, gx = wv.y, fy = wv.z, gy = wv.w;
            const float* sl = cb + l * (H * W);

            const int o  = t & 1;
            const int ta = t - o;
            const int ca = ta + 2 * lane;
            const bool interior = (ta >= 0) & (t + 64 <= W - 1) &
                                  (ry0 >= 0) & (ry0 + 4 <= H - 1);

            float hp0, hp1;

            if (interior) {
                const float* rp = sl + ry0 * W + ca;
                if (o == 0) {
                    {
                        float2 A = __ldg((const float2*)rp);
                        float  c = __ldg(rp + 2);
                        hp0 = fx * A.x + gx * A.y;
                        hp1 = fx * A.y + gx * c;
                    }
                    #pragma unroll
                    for (int j = 1; j <= 4; ++j) {
                        const float* rj = rp + j * W;
                        float2 A = __ldg((const float2*)rj);
                        float  c = __ldg(rj + 2);
                        float hc0 = fx * A.x + gx * A.y;
                        float hc1 = fx * A.y + gx * c;
                        a0[j - 1] += fy * hp0 + gy * hc0;
                        a1[j - 1] += fy * hp1 + gy * hc1;
                        hp0 = hc0; hp1 = hc1;
                    }
                } else {
                    {
                        float2 A = __ldg((const float2*)rp);
                        float2 B = __ldg((const float2*)(rp + 2));
                        hp0 = fx * A.y + gx * B.x;
                        hp1 = fx * B.x + gx * B.y;
                    }
                    #pragma unroll
                    for (int j = 1; j <= 4; ++j) {
                        const float* rj = rp + j * W;
                        float2 A = __ldg((const float2*)rj);
                        float2 B = __ldg((const float2*)(rj + 2));
                        float hc0 = fx * A.y + gx * B.x;
                        float hc1 = fx * B.x + gx * B.y;
                        a0[j - 1] += fy * hp0 + gy * hc0;
                        a1[j - 1] += fy * hp1 + gy * hc1;
                        hp0 = hc0; hp1 = hc1;
                    }
                }
            } else {
                const int c0 = t + 2 * lane;
                const bool cv0 = ((unsigned)c0       < (unsigned)W);
                const bool cv1 = ((unsigned)(c0 + 1) < (unsigned)W);
                const bool cv2 = ((unsigned)(c0 + 2) < (unsigned)W);
                {
                    bool rv = ((unsigned)ry0 < (unsigned)H);
                    const float* rj = sl + ry0 * W + c0;
                    float v0 = (rv && cv0) ? __ldg(rj)     : 0.0f;
                    float v1 = (rv && cv1) ? __ldg(rj + 1) : 0.0f;
                    float v2 = (rv && cv2) ? __ldg(rj + 2) : 0.0f;
                    hp0 = fx * v0 + gx * v1;
                    hp1 = fx * v1 + gx * v2;
                }
                #pragma unroll
                for (int j = 1; j <= 4; ++j) {
                    int row = ry0 + j;
                    bool rv = ((unsigned)row < (unsigned)H);
                    const float* rj = sl + row * W + c0;
                    float v0 = (rv && cv0) ? __ldg(rj)     : 0.0f;
                    float v1 = (rv && cv1) ? __ldg(rj + 1) : 0.0f;
                    float v2 = (rv && cv2) ? __ldg(rj + 2) : 0.0f;
                    float hc0 = fx * v0 + gx * v1;
                    float hc1 = fx * v1 + gx * v2;
                    a0[j - 1] += fy * hp0 + gy * hc0;
                    a1[j - 1] += fy * hp1 + gy * hc1;
                    hp0 = hc0; hp1 = hc1;
                }
            }
        }
    }

    float* ap = g_acc + (size_t)lq * QTRSZ + ((size_t)bk * HP + y0) * WP + x0w + 2 * lane;
    #pragma unroll
    for (int i = 0; i < 4; ++i)
        *(float2*)(ap + i * WP) = make_float2(a0[i], a1[i]);
}

// ---------------------------------------------------------------------------
// Kernel 2: 7x7 PSF convolution (same padding, zeros), sum of 4 acc -> out.
// Block: (32, 8), output tile 32x32. Grid: (6, 6, B*NK).  (R12 version)
// ---------------------------------------------------------------------------
__global__ __launch_bounds__(256) void conv_kernel(
    const float* __restrict__ psf,
    float* __restrict__ out)
{
    __shared__ float s[38 * 40];
    __shared__ float sp[49];

    const int bz = blockIdx.z;
    const float* ap0 = g_acc + (size_t)bz * HP * WP;

    const int tid = threadIdx.y * 32 + threadIdx.x;
    if (tid < 49) sp[tid] = psf[tid];

    const int x0 = blockIdx.x * 32;
    const int y0 = blockIdx.y * 32;

    for (int i = tid; i < 38 * 38; i += 256) {
        int r = i / 38, c = i % 38;
        int gy = y0 + r - 3;
        int gx = x0 + c - 3;
        bool ok = ((unsigned)gy < (unsigned)HP) && ((unsigned)gx < (unsigned)WP);
        int idx = gy * WP + gx;
        float v = 0.0f;
        if (ok) {
            v = ap0[idx] + ap0[idx + QTRSZ] + ap0[idx + 2 * QTRSZ] + ap0[idx + 3 * QTRSZ];
        }
        s[r * 40 + c] = v;
    }
    __syncthreads();

    float w[49];
    #pragma unroll
    for (int i = 0; i < 49; ++i) w[i] = sp[i];

    const int tx = threadIdx.x;
    const int rbase = threadIdx.y * 4;

    float a0 = 0.f, a1 = 0.f, a2 = 0.f, a3 = 0.f;
    #pragma unroll
    for (int rr = 0; rr < 10; ++rr) {
        #pragma unroll
        for (int v = 0; v < 7; ++v) {
            float xv = s[(rbase + rr) * 40 + tx + v];
            if (rr <= 6)            a0 += w[rr * 7 + v] * xv;
            if (rr >= 1 && rr <= 7) a1 += w[(rr - 1) * 7 + v] * xv;
            if (rr >= 2 && rr <= 8) a2 += w[(rr - 2) * 7 + v] * xv;
            if (rr >= 3)            a3 += w[(rr - 3) * 7 + v] * xv;
        }
    }

    float* op = out + ((size_t)bz * HP + y0 + rbase) * WP + x0 + tx;
    op[0 * WP] = a0;
    op[1 * WP] = a1;
    op[2 * WP] = a2;
    op[3 * WP] = a3;
}

extern "C" void kernel_launch(void* const* d_in, const int* in_sizes, int n_in,
                              void* d_out, int out_size)
{
    const float* cube = (const float*)d_in[0];
    const float* psf  = (const float*)d_in[1];
    const float* dx   = (const float*)d_in[2];
    const float* dy   = (const float*)d_in[3];
    float* out = (float*)d_out;

    dim3 ga(1, 24, BATCH * NK * 4), ta(32, 6);   // 6144 blocks, 192 thr
    accum_kernel<<<ga, ta>>>(cube, dx, dy);

    dim3 gc(6, 6, BATCH * NK), tc(32, 8);
    conv_kernel<<<gc, tc>>>(psf, out);
}